// round 15
// baseline (speedup 1.0000x reference)
#include <cuda_runtime.h>

#define TPB   128
#define NR    32768
#define DD    64
#define HH    8
#define PP    14
#define KB    5
#define NCH   8            // dim chunks; chunk c owns dims ≡ c (mod 8)
#define NRB   (NR / TPB)   // 256 row-blocks
#define BBf   5.0f
#define MINW  0.001f
#define MINH  0.001f
#define MIND  0.001f
#define XST   65           // padded smem stride -> conflict-free column reads
#define BLOB  728          // u64 per (chunk,k4) blob: w2[64] w3[128] b1[8] b2[8] b3[16] w1[<=504]
#define OFF_W2 0
#define OFF_W3 64
#define OFF_B1 192
#define OFF_B2 200
#define OFF_B3 208
#define OFF_W1 224

typedef unsigned long long u64;

// prepacked weights: 32 blobs of 728 u64 (pidx = k4*8 + chunk), pair (da, da+8)
__device__ __align__(16) u64 g_pack[32 * BLOB];

__device__ __forceinline__ u64 ffma2(u64 a, u64 b, u64 c){
    u64 d; asm("fma.rn.f32x2 %0, %1, %2, %3;" : "=l"(d) : "l"(a), "l"(b), "l"(c)); return d;
}
__device__ __forceinline__ u64 pack2(float lo, float hi){
    u64 d; asm("mov.b64 %0, {%1, %2};" : "=l"(d) : "f"(lo), "f"(hi)); return d;
}
__device__ __forceinline__ void unpack2(u64 v, float& lo, float& hi){
    asm("mov.b64 {%0, %1}, %2;" : "=f"(lo), "=f"(hi) : "l"(v));
}
__device__ __forceinline__ float tanh_fast(float x){
    float y; asm("tanh.approx.f32 %0, %1;" : "=f"(y) : "f"(x)); return y;
}

// ---------------- prepack kernel: interleave (lo,hi) weight pairs ----------------
__global__ void prepack_kernel(const float* __restrict__ W1, const float* __restrict__ b1,
                               const float* __restrict__ W2, const float* __restrict__ b2,
                               const float* __restrict__ W3, const float* __restrict__ b3)
{
    const int pidx  = blockIdx.x;        // k4*8 + chunk
    const int k4    = pidx >> 3;
    const int chunk = pidx & 7;
    const int da = chunk + 16 * k4;
    const int la = da - 1;               // may be -1 (lo lane zeros)
    const int lb = da + 7;
    u64* dst = g_pack + (size_t)pidx * BLOB;
    const int tid = threadIdx.x;

    if (tid < 64){
        float lo = (la >= 0) ? W2[la * 64 + tid] : 0.f;
        dst[OFF_W2 + tid] = pack2(lo, W2[lb * 64 + tid]);
    }
    if (tid < 128){                      // w3: 8 rows x 16 padded cols
        int g = tid >> 4, c = tid & 15;
        u64 v = 0ULL;
        if (c < PP){
            float lo = (la >= 0) ? W3[la * (HH*PP) + g * PP + c] : 0.f;
            v = pack2(lo, W3[lb * (HH*PP) + g * PP + c]);
        }
        dst[OFF_W3 + tid] = v;
    }
    if (tid < HH){
        float l1v = (la >= 0) ? b1[la * HH + tid] : 0.f;
        dst[OFF_B1 + tid] = pack2(l1v, b1[lb * HH + tid]);
        float l2v = (la >= 0) ? b2[la * HH + tid] : 0.f;
        dst[OFF_B2 + tid] = pack2(l2v, b2[lb * HH + tid]);
    }
    if (tid < 16){
        u64 v = 0ULL;
        if (tid < PP){
            float lo = (la >= 0) ? b3[la * PP + tid] : 0.f;
            v = pack2(lo, b3[lb * PP + tid]);
        }
        dst[OFF_B3 + tid] = v;
    }
    const int n1 = (lb + 1) * HH;
    const float* W1a = W1 + (size_t)la * (63*HH);
    const float* W1b = W1 + (size_t)lb * (63*HH);
    for (int e = tid; e < n1; e += blockDim.x){
        float lo = (la >= 0) ? W1a[e] : 0.f;   // input W1 is pre-masked: rows > la are 0
        dst[OFF_W1 + e] = pack2(lo, W1b[e]);
    }
}

// Two independent RQS evaluations, interleaved for 2-way ILP through MUFU chains.
__device__ __forceinline__ void rqs_eval2(const float* pa, float xa,
                                          const float* pb, float xb,
                                          float& za, float& lda,
                                          float& zb, float& ldb)
{
    bool ina = (xa >= -BBf) && (xa <= BBf);
    bool inb = (xb >= -BBf) && (xb <= BBf);
    float xca = fminf(fmaxf(xa, -BBf), BBf);
    float xcb = fminf(fmaxf(xb, -BBf), BBf);

    float ewa[KB], eha[KB], ewb[KB], ehb[KB];
    float swa = 0.f, sha = 0.f, swb = 0.f, shb = 0.f;
#pragma unroll
    for (int k = 0; k < KB; k++){
        ewa[k] = __expf(pa[k]);      ewb[k] = __expf(pb[k]);
        swa += ewa[k];               swb += ewb[k];
    }
#pragma unroll
    for (int k = 0; k < KB; k++){
        eha[k] = __expf(pa[KB + k]); ehb[k] = __expf(pb[KB + k]);
        sha += eha[k];               shb += ehb[k];
    }
    float aWa = __fdividef(1.0f - KB * MINW, swa);
    float aWb = __fdividef(1.0f - KB * MINW, swb);
    float aHa = __fdividef(1.0f - KB * MINH, sha);
    float aHb = __fdividef(1.0f - KB * MINH, shb);

    float cwa = -BBf, cha = -BBf, cwb = -BBf, chb = -BBf;
    float icwa = -BBf, icha = -BBf, ibwa = 1.f, iha = 1.f;
    float icwb = -BBf, ichb = -BBf, ibwb = 1.f, ihb = 1.f;
    float duLa = 0.f, duRa = 0.f, duLb = 0.f, duRb = 0.f;
    bool fba = true, lba = false, fbb = true, lbb = false;
#pragma unroll
    for (int k = 0; k < KB; k++){
        float nwa = (k == KB-1) ? BBf : cwa + 2.0f * BBf * (MINW + aWa * ewa[k]);
        float nwb = (k == KB-1) ? BBf : cwb + 2.0f * BBf * (MINW + aWb * ewb[k]);
        float nha = (k == KB-1) ? BBf : cha + 2.0f * BBf * (MINH + aHa * eha[k]);
        float nhb = (k == KB-1) ? BBf : chb + 2.0f * BBf * (MINH + aHb * ehb[k]);
        bool ca = (k == 0) || (xca >= cwa);
        bool cb = (k == 0) || (xcb >= cwb);
        if (ca){
            icwa = cwa; icha = cha; ibwa = nwa - cwa; iha = nha - cha;
            fba = (k == 0); lba = (k == KB-1);
            duLa = (k == 0)    ? 0.f : pa[2*KB + k - 1];
            duRa = (k == KB-1) ? 0.f : pa[2*KB + k];
        }
        if (cb){
            icwb = cwb; ichb = chb; ibwb = nwb - cwb; ihb = nhb - chb;
            fbb = (k == 0); lbb = (k == KB-1);
            duLb = (k == 0)    ? 0.f : pb[2*KB + k - 1];
            duRb = (k == KB-1) ? 0.f : pb[2*KB + k];
        }
        cwa = nwa; cha = nha; cwb = nwb; chb = nhb;
    }
    float idva  = fba ? 1.0f : (MIND + __logf(1.0f + __expf(duLa)));
    float idvb  = fbb ? 1.0f : (MIND + __logf(1.0f + __expf(duLb)));
    float idp1a = lba ? 1.0f : (MIND + __logf(1.0f + __expf(duRa)));
    float idp1b = lbb ? 1.0f : (MIND + __logf(1.0f + __expf(duRb)));

    float rba = __fdividef(1.0f, ibwa);
    float rbb = __fdividef(1.0f, ibwb);
    float tha = (xca - icwa) * rba;
    float thb = (xcb - icwb) * rbb;
    float idla = iha * rba;
    float idlb = ihb * rbb;
    float tma = tha * (1.0f - tha);
    float tmb = thb * (1.0f - thb);
    float t2a = tha * tha;
    float t2b = thb * thb;
    float numa = iha * (idla * t2a + idva * tma);
    float numb = ihb * (idlb * t2b + idvb * tmb);
    float dena = idla + (idva + idp1a - 2.0f * idla) * tma;
    float denb = idlb + (idvb + idp1b - 2.0f * idlb) * tmb;
    float outa = icha + __fdividef(numa, dena);
    float outb = ichb + __fdividef(numb, denb);
    float oma = 1.0f - tha;
    float omb = 1.0f - thb;
    float dna = idla * idla * (idp1a * t2a + 2.0f * idla * tma + idva * oma * oma);
    float dnb = idlb * idlb * (idp1b * t2b + 2.0f * idlb * tmb + idvb * omb * omb);
    float lva = __logf(dna) - 2.0f * __logf(dena);
    float lvb = __logf(dnb) - 2.0f * __logf(denb);

    za  = ina ? outa : xa;
    zb  = inb ? outb : xb;
    lda = ina ? lva  : 0.0f;
    ldb = inb ? lvb  : 0.0f;
}

__global__ __launch_bounds__(TPB, 6)
void nsf_ar_kernel(const float* __restrict__ x,
                   const float* __restrict__ initp,
                   float* __restrict__ out)
{
    __shared__ __align__(16) float xsh[TPB * XST];   // 33,280 B: only x lives in smem
    __shared__ float redbuf[2][8];

    const int tid    = threadIdx.x;
    const int warp   = tid >> 5;
    const int bid    = blockIdx.x;          // 0..2047
    const int rowblk = bid & (NRB - 1);     // 0..255
    const int chunk  = bid >> 8;            // 0..7
    const int row0   = rowblk * TPB;
    const int row    = row0 + tid;

    // stage x tile with float4 global reads, padded smem writes
    {
        const float4* X4 = (const float4*)(x + (size_t)row0 * DD);
        for (int i = tid; i < TPB * DD / 4; i += TPB){
            float4 v = X4[i];
            int r = i >> 4, c = (i & 15) * 4;
            float* d = &xsh[r * XST + c];
            d[0] = v.x; d[1] = v.y; d[2] = v.z; d[3] = v.w;
        }
    }
    __syncthreads();

    const float* xr = &xsh[tid * XST];
    float* out2 = out + (size_t)NR * DD;

#pragma unroll
    for (int k4 = 0; k4 < 4; k4++){
        const int da = chunk + 16 * k4;
        const int db = da + 8;
        const int lb = db - 1;
        // weights read straight from L1-resident prepacked global (uniform LDG)
        const u64* wb = g_pack + (size_t)(k4 * 8 + chunk) * BLOB;

        // ---- layer 1 (paired dims): a1p[h] += (x, x) * (w_da, w_db) ----
        u64 a1p[HH];
#pragma unroll
        for (int h = 0; h < HH; h++) a1p[h] = __ldg(wb + OFF_B1 + h);
#pragma unroll 4
        for (int j = 0; j <= lb; j++){
            float xv = xr[j];
            u64 xp = pack2(xv, xv);
            const ulonglong2* wp = reinterpret_cast<const ulonglong2*>(wb + OFF_W1 + j * 8);
            ulonglong2 q0 = __ldg(wp), q1 = __ldg(wp + 1), q2 = __ldg(wp + 2), q3 = __ldg(wp + 3);
            a1p[0] = ffma2(xp, q0.x, a1p[0]); a1p[1] = ffma2(xp, q0.y, a1p[1]);
            a1p[2] = ffma2(xp, q1.x, a1p[2]); a1p[3] = ffma2(xp, q1.y, a1p[3]);
            a1p[4] = ffma2(xp, q2.x, a1p[4]); a1p[5] = ffma2(xp, q2.y, a1p[5]);
            a1p[6] = ffma2(xp, q3.x, a1p[6]); a1p[7] = ffma2(xp, q3.y, a1p[7]);
        }
#pragma unroll
        for (int h = 0; h < HH; h++){
            float lo, hi; unpack2(a1p[h], lo, hi);
            a1p[h] = pack2(tanh_fast(lo), tanh_fast(hi));
        }

        // ---- layer 2 (paired) ----
        u64 a2p[HH];
#pragma unroll
        for (int g = 0; g < HH; g++) a2p[g] = __ldg(wb + OFF_B2 + g);
#pragma unroll
        for (int h = 0; h < HH; h++){
            u64 hv = a1p[h];
            const ulonglong2* wp = reinterpret_cast<const ulonglong2*>(wb + OFF_W2 + h * 8);
            ulonglong2 q0 = __ldg(wp), q1 = __ldg(wp + 1), q2 = __ldg(wp + 2), q3 = __ldg(wp + 3);
            a2p[0] = ffma2(hv, q0.x, a2p[0]); a2p[1] = ffma2(hv, q0.y, a2p[1]);
            a2p[2] = ffma2(hv, q1.x, a2p[2]); a2p[3] = ffma2(hv, q1.y, a2p[3]);
            a2p[4] = ffma2(hv, q2.x, a2p[4]); a2p[5] = ffma2(hv, q2.y, a2p[5]);
            a2p[6] = ffma2(hv, q3.x, a2p[6]); a2p[7] = ffma2(hv, q3.y, a2p[7]);
        }
#pragma unroll
        for (int g = 0; g < HH; g++){
            float lo, hi; unpack2(a2p[g], lo, hi);
            a2p[g] = pack2(tanh_fast(lo), tanh_fast(hi));
        }

        // ---- layer 3 (paired, 16 padded outputs) ----
        u64 pu[16];
#pragma unroll
        for (int c = 0; c < 16; c++) pu[c] = __ldg(wb + OFF_B3 + c);
#pragma unroll
        for (int g = 0; g < HH; g++){
            u64 gv = a2p[g];
            const ulonglong2* wp = reinterpret_cast<const ulonglong2*>(wb + OFF_W3 + g * 16);
            ulonglong2 q0 = __ldg(wp),     q1 = __ldg(wp + 1), q2 = __ldg(wp + 2), q3 = __ldg(wp + 3);
            ulonglong2 q4 = __ldg(wp + 4), q5 = __ldg(wp + 5), q6 = __ldg(wp + 6);
            pu[0]  = ffma2(gv, q0.x, pu[0]);  pu[1]  = ffma2(gv, q0.y, pu[1]);
            pu[2]  = ffma2(gv, q1.x, pu[2]);  pu[3]  = ffma2(gv, q1.y, pu[3]);
            pu[4]  = ffma2(gv, q2.x, pu[4]);  pu[5]  = ffma2(gv, q2.y, pu[5]);
            pu[6]  = ffma2(gv, q3.x, pu[6]);  pu[7]  = ffma2(gv, q3.y, pu[7]);
            pu[8]  = ffma2(gv, q4.x, pu[8]);  pu[9]  = ffma2(gv, q4.y, pu[9]);
            pu[10] = ffma2(gv, q5.x, pu[10]); pu[11] = ffma2(gv, q5.y, pu[11]);
            pu[12] = ffma2(gv, q6.x, pu[12]); pu[13] = ffma2(gv, q6.y, pu[13]);
        }

        // ---- unpack params, run both splines (interleaved) ----
        float pa[PP], pb[PP];
#pragma unroll
        for (int c = 0; c < PP; c++) unpack2(pu[c], pa[c], pb[c]);
        if (da == 0){
#pragma unroll
            for (int c = 0; c < PP; c++) pa[c] = initp[c];
        }

        float za, lda, zb, ldb;
        rqs_eval2(pa, xr[da], pb, xr[db], za, lda, zb, ldb);
        out[(size_t)da * NR + row] = za;
        out[(size_t)db * NR + row] = zb;

        // ---- logdet partial sums: warp-pair reduction via named barriers ----
#pragma unroll
        for (int o = 16; o > 0; o >>= 1){
            lda += __shfl_down_sync(0xffffffffu, lda, o);
            ldb += __shfl_down_sync(0xffffffffu, ldb, o);
        }
        const int par = k4 & 1;                 // parity double-buffer across k4
        if ((tid & 31) == 0){
            redbuf[par][warp]     = lda;
            redbuf[par][4 + warp] = ldb;
        }
        const int grp = warp >> 1;              // 0: warps 0,1  |  1: warps 2,3
        asm volatile("bar.sync %0, 64;" :: "r"(1 + grp) : "memory");
        if ((tid & 63) == 0){
            out2[da * (NR/64) + rowblk * 2 + grp] =
                redbuf[par][2*grp]     + redbuf[par][2*grp + 1];
            out2[db * (NR/64) + rowblk * 2 + grp] =
                redbuf[par][4 + 2*grp] + redbuf[par][4 + 2*grp + 1];
        }
        // redbuf reuse across k4 is parity-protected; no block barriers in the loop
    }
}

extern "C" void kernel_launch(void* const* d_in, const int* in_sizes, int n_in,
                              void* d_out, int out_size)
{
    const float* x     = (const float*)d_in[0];
    const float* initp = (const float*)d_in[1];
    const float* W1    = (const float*)d_in[2];
    const float* b1    = (const float*)d_in[3];
    const float* W2    = (const float*)d_in[4];
    const float* b2    = (const float*)d_in[5];
    const float* W3    = (const float*)d_in[6];
    const float* b3    = (const float*)d_in[7];
    float* out = (float*)d_out;

    prepack_kernel<<<32, TPB>>>(W1, b1, W2, b2, W3, b3);
    nsf_ar_kernel<<<NRB * NCH, TPB>>>(x, initp, out);
}

// round 16
// speedup vs baseline: 1.0266x; 1.0266x over previous
#include <cuda_runtime.h>

#define TPB   128
#define NR    32768
#define DD    64
#define HH    8
#define PP    14
#define KB    5
#define NCH   16           // dim chunks; chunk c owns dims {c, c+16, c+32, c+48}
#define NRB   128          // row-blocks of 256 rows
#define ROWS  256          // rows per CTA (2 per thread)
#define BBf   5.0f
#define MINW  0.001f
#define MINH  0.001f
#define MIND  0.001f
#define XT_ST 257          // transposed-x smem stride (padded): xt[j*XT_ST + r]
#define BLOB  736          // u64 per pair blob: w2[64] w3[128] b1[8] b2[8] b3[16] w1[<=504]
#define OFF_W2 0
#define OFF_W3 64
#define OFF_B1 192
#define OFF_B2 200
#define OFF_B3 208
#define OFF_W1 224

#define SMEM_XT    (DD * XT_ST * 4)                    // 65792
#define SMEM_WBUF  (1200 * 8)                          // 9600 (both blobs, worst case)
#define SMEM_TOTAL (SMEM_XT + SMEM_WBUF + 16 + 128)    // + mbar + redbuf

typedef unsigned long long u64;

// prepacked weights: 32 blobs (pidx = kp*16 + chunk), pair (da, da+16), da = chunk + 32*kp
__device__ __align__(16) u64 g_pack[32 * BLOB];

__device__ __forceinline__ u64 ffma2(u64 a, u64 b, u64 c){
    u64 d; asm("fma.rn.f32x2 %0, %1, %2, %3;" : "=l"(d) : "l"(a), "l"(b), "l"(c)); return d;
}
__device__ __forceinline__ u64 pack2(float lo, float hi){
    u64 d; asm("mov.b64 %0, {%1, %2};" : "=l"(d) : "f"(lo), "f"(hi)); return d;
}
__device__ __forceinline__ void unpack2(u64 v, float& lo, float& hi){
    asm("mov.b64 {%0, %1}, %2;" : "=f"(lo), "=f"(hi) : "l"(v));
}
__device__ __forceinline__ float tanh_fast(float x){
    float y; asm("tanh.approx.f32 %0, %1;" : "=f"(y) : "f"(x)); return y;
}
__device__ __forceinline__ unsigned smem_u32(const void* p){
    return (unsigned)__cvta_generic_to_shared(p);
}
__device__ __forceinline__ void mbar_init(unsigned a, unsigned cnt){
    asm volatile("mbarrier.init.shared.b64 [%0], %1;" :: "r"(a), "r"(cnt) : "memory");
}
__device__ __forceinline__ void mbar_expect_tx(unsigned a, unsigned bytes){
    asm volatile("mbarrier.arrive.expect_tx.shared.b64 _, [%0], %1;" :: "r"(a), "r"(bytes) : "memory");
}
__device__ __forceinline__ void mbar_wait(unsigned a, unsigned phase){
    asm volatile(
        "{\n\t.reg .pred P;\n\t"
        "WAITLP_%=:\n\t"
        "mbarrier.try_wait.parity.acquire.cta.shared::cta.b64 P, [%0], %1, 0x989680;\n\t"
        "@P bra.uni WAITDN_%=;\n\t"
        "bra.uni WAITLP_%=;\n\t"
        "WAITDN_%=:\n\t}"
        :: "r"(a), "r"(phase) : "memory");
}
__device__ __forceinline__ void bulk_g2s(unsigned dst, const void* src, unsigned bytes, unsigned mbar){
    asm volatile(
        "cp.async.bulk.shared::cta.global.mbarrier::complete_tx::bytes [%0], [%1], %2, [%3];"
        :: "r"(dst), "l"(src), "r"(bytes), "r"(mbar) : "memory");
}

// ---------------- prepack kernel: interleave (lo,hi) weight pairs ----------------
__global__ void prepack_kernel(const float* __restrict__ W1, const float* __restrict__ b1,
                               const float* __restrict__ W2, const float* __restrict__ b2,
                               const float* __restrict__ W3, const float* __restrict__ b3)
{
    const int pidx  = blockIdx.x;        // kp*16 + chunk
    const int kp    = pidx >> 4;
    const int chunk = pidx & 15;
    const int da = chunk + 32 * kp;      // lo dim of pair (da, da+16)
    const int la = da - 1;               // may be -1 (lo lane zeros)
    const int lb = da + 15;              // (da+16) - 1, max 62
    u64* dst = g_pack + (size_t)pidx * BLOB;
    const int tid = threadIdx.x;

    if (tid < 64){
        float lo = (la >= 0) ? W2[la * 64 + tid] : 0.f;
        dst[OFF_W2 + tid] = pack2(lo, W2[lb * 64 + tid]);
    }
    if (tid < 128){                      // w3: 8 rows x 16 padded cols
        int g = tid >> 4, c = tid & 15;
        u64 v = 0ULL;
        if (c < PP){
            float lo = (la >= 0) ? W3[la * (HH*PP) + g * PP + c] : 0.f;
            v = pack2(lo, W3[lb * (HH*PP) + g * PP + c]);
        }
        dst[OFF_W3 + tid] = v;
    }
    if (tid < HH){
        float l1v = (la >= 0) ? b1[la * HH + tid] : 0.f;
        dst[OFF_B1 + tid] = pack2(l1v, b1[lb * HH + tid]);
        float l2v = (la >= 0) ? b2[la * HH + tid] : 0.f;
        dst[OFF_B2 + tid] = pack2(l2v, b2[lb * HH + tid]);
    }
    if (tid < 16){
        u64 v = 0ULL;
        if (tid < PP){
            float lo = (la >= 0) ? b3[la * PP + tid] : 0.f;
            v = pack2(lo, b3[lb * PP + tid]);
        }
        dst[OFF_B3 + tid] = v;
    }
    const int n1 = (lb + 1) * HH;        // <= 504
    const float* W1a = W1 + (size_t)la * (63*HH);
    const float* W1b = W1 + (size_t)lb * (63*HH);
    for (int e = tid; e < n1; e += blockDim.x){
        float lo = (la >= 0) ? W1a[e] : 0.f;   // input W1 is pre-masked: rows > la are 0
        dst[OFF_W1 + e] = pack2(lo, W1b[e]);
    }
}

// Two independent RQS evaluations, interleaved for 2-way ILP through MUFU chains.
__device__ __forceinline__ void rqs_eval2(const float* pa, float xa,
                                          const float* pb, float xb,
                                          float& za, float& lda,
                                          float& zb, float& ldb)
{
    bool ina = (xa >= -BBf) && (xa <= BBf);
    bool inb = (xb >= -BBf) && (xb <= BBf);
    float xca = fminf(fmaxf(xa, -BBf), BBf);
    float xcb = fminf(fmaxf(xb, -BBf), BBf);

    float ewa[KB], eha[KB], ewb[KB], ehb[KB];
    float swa = 0.f, sha = 0.f, swb = 0.f, shb = 0.f;
#pragma unroll
    for (int k = 0; k < KB; k++){
        ewa[k] = __expf(pa[k]);      ewb[k] = __expf(pb[k]);
        swa += ewa[k];               swb += ewb[k];
    }
#pragma unroll
    for (int k = 0; k < KB; k++){
        eha[k] = __expf(pa[KB + k]); ehb[k] = __expf(pb[KB + k]);
        sha += eha[k];               shb += ehb[k];
    }
    float aWa = __fdividef(1.0f - KB * MINW, swa);
    float aWb = __fdividef(1.0f - KB * MINW, swb);
    float aHa = __fdividef(1.0f - KB * MINH, sha);
    float aHb = __fdividef(1.0f - KB * MINH, shb);

    float cwa = -BBf, cha = -BBf, cwb = -BBf, chb = -BBf;
    float icwa = -BBf, icha = -BBf, ibwa = 1.f, iha = 1.f;
    float icwb = -BBf, ichb = -BBf, ibwb = 1.f, ihb = 1.f;
    float duLa = 0.f, duRa = 0.f, duLb = 0.f, duRb = 0.f;
    bool fba = true, lba = false, fbb = true, lbb = false;
#pragma unroll
    for (int k = 0; k < KB; k++){
        float nwa = (k == KB-1) ? BBf : cwa + 2.0f * BBf * (MINW + aWa * ewa[k]);
        float nwb = (k == KB-1) ? BBf : cwb + 2.0f * BBf * (MINW + aWb * ewb[k]);
        float nha = (k == KB-1) ? BBf : cha + 2.0f * BBf * (MINH + aHa * eha[k]);
        float nhb = (k == KB-1) ? BBf : chb + 2.0f * BBf * (MINH + aHb * ehb[k]);
        bool ca = (k == 0) || (xca >= cwa);
        bool cb = (k == 0) || (xcb >= cwb);
        if (ca){
            icwa = cwa; icha = cha; ibwa = nwa - cwa; iha = nha - cha;
            fba = (k == 0); lba = (k == KB-1);
            duLa = (k == 0)    ? 0.f : pa[2*KB + k - 1];
            duRa = (k == KB-1) ? 0.f : pa[2*KB + k];
        }
        if (cb){
            icwb = cwb; ichb = chb; ibwb = nwb - cwb; ihb = nhb - chb;
            fbb = (k == 0); lbb = (k == KB-1);
            duLb = (k == 0)    ? 0.f : pb[2*KB + k - 1];
            duRb = (k == KB-1) ? 0.f : pb[2*KB + k];
        }
        cwa = nwa; cha = nha; cwb = nwb; chb = nhb;
    }
    float idva  = fba ? 1.0f : (MIND + __logf(1.0f + __expf(duLa)));
    float idvb  = fbb ? 1.0f : (MIND + __logf(1.0f + __expf(duLb)));
    float idp1a = lba ? 1.0f : (MIND + __logf(1.0f + __expf(duRa)));
    float idp1b = lbb ? 1.0f : (MIND + __logf(1.0f + __expf(duRb)));

    float rba = __fdividef(1.0f, ibwa);
    float rbb = __fdividef(1.0f, ibwb);
    float tha = (xca - icwa) * rba;
    float thb = (xcb - icwb) * rbb;
    float idla = iha * rba;
    float idlb = ihb * rbb;
    float tma = tha * (1.0f - tha);
    float tmb = thb * (1.0f - thb);
    float t2a = tha * tha;
    float t2b = thb * thb;
    float numa = iha * (idla * t2a + idva * tma);
    float numb = ihb * (idlb * t2b + idvb * tmb);
    float dena = idla + (idva + idp1a - 2.0f * idla) * tma;
    float denb = idlb + (idvb + idp1b - 2.0f * idlb) * tmb;
    float outa = icha + __fdividef(numa, dena);
    float outb = ichb + __fdividef(numb, denb);
    float oma = 1.0f - tha;
    float omb = 1.0f - thb;
    float dna = idla * idla * (idp1a * t2a + 2.0f * idla * tma + idva * oma * oma);
    float dnb = idlb * idlb * (idp1b * t2b + 2.0f * idlb * tmb + idvb * omb * omb);
    float lva = __logf(dna) - 2.0f * __logf(dena);
    float lvb = __logf(dnb) - 2.0f * __logf(denb);

    za  = ina ? outa : xa;
    zb  = inb ? outb : xb;
    lda = ina ? lva  : 0.0f;
    ldb = inb ? lvb  : 0.0f;
}

// Tail for one row: tanh -> layer2 -> layer3 -> both splines. a1 passed as a
// reference to a STATICALLY NAMED register array at each call site (never a
// runtime-selected pointer -> stays in registers after inlining).
__device__ __forceinline__ void tail_row(const u64* __restrict__ wb,
                                         const u64 (&a1)[HH],
                                         const float* __restrict__ xrow,  // element j at xrow[j*XT_ST]
                                         int da, int db, int row,
                                         const float* __restrict__ initp,
                                         float* __restrict__ out,
                                         float& ld_a, float& ld_b)
{
    u64 a1t[HH];
#pragma unroll
    for (int h = 0; h < HH; h++){
        float lo, hi; unpack2(a1[h], lo, hi);
        a1t[h] = pack2(tanh_fast(lo), tanh_fast(hi));
    }

    u64 a2[HH];
#pragma unroll
    for (int g = 0; g < HH; g++) a2[g] = wb[OFF_B2 + g];
#pragma unroll
    for (int h = 0; h < HH; h++){
        u64 hv = a1t[h];
        const ulonglong2* wp = reinterpret_cast<const ulonglong2*>(wb + OFF_W2 + h * 8);
        ulonglong2 q0 = wp[0], q1 = wp[1], q2 = wp[2], q3 = wp[3];
        a2[0] = ffma2(hv, q0.x, a2[0]); a2[1] = ffma2(hv, q0.y, a2[1]);
        a2[2] = ffma2(hv, q1.x, a2[2]); a2[3] = ffma2(hv, q1.y, a2[3]);
        a2[4] = ffma2(hv, q2.x, a2[4]); a2[5] = ffma2(hv, q2.y, a2[5]);
        a2[6] = ffma2(hv, q3.x, a2[6]); a2[7] = ffma2(hv, q3.y, a2[7]);
    }
#pragma unroll
    for (int g = 0; g < HH; g++){
        float lo, hi; unpack2(a2[g], lo, hi);
        a2[g] = pack2(tanh_fast(lo), tanh_fast(hi));
    }

    u64 pu[16];
#pragma unroll
    for (int c = 0; c < 16; c++) pu[c] = wb[OFF_B3 + c];
#pragma unroll
    for (int g = 0; g < HH; g++){
        u64 gv = a2[g];
        const ulonglong2* wp = reinterpret_cast<const ulonglong2*>(wb + OFF_W3 + g * 16);
        ulonglong2 q0 = wp[0], q1 = wp[1], q2 = wp[2], q3 = wp[3];
        ulonglong2 q4 = wp[4], q5 = wp[5], q6 = wp[6];
        pu[0]  = ffma2(gv, q0.x, pu[0]);  pu[1]  = ffma2(gv, q0.y, pu[1]);
        pu[2]  = ffma2(gv, q1.x, pu[2]);  pu[3]  = ffma2(gv, q1.y, pu[3]);
        pu[4]  = ffma2(gv, q2.x, pu[4]);  pu[5]  = ffma2(gv, q2.y, pu[5]);
        pu[6]  = ffma2(gv, q3.x, pu[6]);  pu[7]  = ffma2(gv, q3.y, pu[7]);
        pu[8]  = ffma2(gv, q4.x, pu[8]);  pu[9]  = ffma2(gv, q4.y, pu[9]);
        pu[10] = ffma2(gv, q5.x, pu[10]); pu[11] = ffma2(gv, q5.y, pu[11]);
        pu[12] = ffma2(gv, q6.x, pu[12]); pu[13] = ffma2(gv, q6.y, pu[13]);
    }

    float pa[PP], pb[PP];
#pragma unroll
    for (int c = 0; c < PP; c++) unpack2(pu[c], pa[c], pb[c]);
    if (da == 0){
#pragma unroll
        for (int c = 0; c < PP; c++) pa[c] = initp[c];
    }

    float za, lda, zb, ldb;
    rqs_eval2(pa, xrow[da * XT_ST], pb, xrow[db * XT_ST], za, lda, zb, ldb);
    out[(size_t)da * NR + row] = za;
    out[(size_t)db * NR + row] = zb;
    ld_a = lda; ld_b = ldb;
}

__global__ __launch_bounds__(TPB, 3)
void nsf_ar_kernel(const float* __restrict__ x,
                   const float* __restrict__ initp,
                   float* __restrict__ out)
{
    extern __shared__ __align__(16) char smem[];
    float* xt   = (float*)smem;                              // [DD][XT_ST] transposed x
    u64*   wbuf = (u64*)(smem + SMEM_XT);                    // both pair blobs
    u64*   mbar = (u64*)(smem + SMEM_XT + SMEM_WBUF);        // 1 mbarrier
    float* redf = (float*)(smem + SMEM_XT + SMEM_WBUF + 16); // [2][16]

    const int tid    = threadIdx.x;
    const int warp   = tid >> 5;
    const int bid    = blockIdx.x;          // 0..2047
    const int chunk  = bid & (NCH - 1);     // 0..15
    const int rowblk = bid >> 4;            // 0..127
    const int row0   = rowblk * ROWS;
    const int rowA   = row0 + tid;
    const int rowB   = row0 + 128 + tid;

    const unsigned a_mbar = smem_u32(mbar);
    if (tid == 0) mbar_init(a_mbar, 1);

    // stage x tile TRANSPOSED: xt[j*XT_ST + r] (padded stride: staging ~2-way, reads conflict-free)
    {
        const float4* X4 = (const float4*)(x + (size_t)row0 * DD);
        for (int i = tid; i < ROWS * DD / 4; i += TPB){
            float4 v = X4[i];
            int r = i >> 4, c = (i & 15) * 4;
            xt[(c + 0) * XT_ST + r] = v.x;
            xt[(c + 1) * XT_ST + r] = v.y;
            xt[(c + 2) * XT_ST + r] = v.z;
            xt[(c + 3) * XT_ST + r] = v.w;
        }
    }
    __syncthreads();   // mbar init + xt visible

    const unsigned S0u = 224 + (chunk + 16) * HH;            // blob0 size in u64
    if (tid == 0){
        asm volatile("fence.proxy.async.shared::cta;" ::: "memory");
        unsigned sz0 = S0u * 8;
        unsigned sz1 = (224 + (chunk + 48) * HH) * 8;
        mbar_expect_tx(a_mbar, sz0 + sz1);
        bulk_g2s(smem_u32(wbuf),       (const void*)(g_pack + (size_t)chunk * BLOB),        sz0, a_mbar);
        bulk_g2s(smem_u32(wbuf) + sz0, (const void*)(g_pack + (size_t)(16 + chunk) * BLOB), sz1, a_mbar);
    }
    mbar_wait(a_mbar, 0);

    const float* xrowA = xt + tid;
    const float* xrowB = xt + 128 + tid;
    float* out2 = out + (size_t)NR * DD;

#pragma unroll
    for (int kp = 0; kp < 2; kp++){
        const int da = chunk + 32 * kp;
        const int db = da + 16;
        const int lb = da + 15;
        const u64* wb = kp ? (wbuf + S0u) : wbuf;

        // ---- layer 1: both rows share every weight fetch ----
        u64 a1A[HH], a1B[HH];
#pragma unroll
        for (int h = 0; h < HH; h++){ u64 b = wb[OFF_B1 + h]; a1A[h] = b; a1B[h] = b; }
#pragma unroll 2
        for (int j = 0; j <= lb; j++){
            float xa = xrowA[j * XT_ST], xb = xrowB[j * XT_ST];
            u64 xpA = pack2(xa, xa), xpB = pack2(xb, xb);
            const ulonglong2* wp = reinterpret_cast<const ulonglong2*>(wb + OFF_W1 + j * 8);
            ulonglong2 q0 = wp[0], q1 = wp[1], q2 = wp[2], q3 = wp[3];
            a1A[0] = ffma2(xpA, q0.x, a1A[0]); a1B[0] = ffma2(xpB, q0.x, a1B[0]);
            a1A[1] = ffma2(xpA, q0.y, a1A[1]); a1B[1] = ffma2(xpB, q0.y, a1B[1]);
            a1A[2] = ffma2(xpA, q1.x, a1A[2]); a1B[2] = ffma2(xpB, q1.x, a1B[2]);
            a1A[3] = ffma2(xpA, q1.y, a1A[3]); a1B[3] = ffma2(xpB, q1.y, a1B[3]);
            a1A[4] = ffma2(xpA, q2.x, a1A[4]); a1B[4] = ffma2(xpB, q2.x, a1B[4]);
            a1A[5] = ffma2(xpA, q2.y, a1A[5]); a1B[5] = ffma2(xpB, q2.y, a1B[5]);
            a1A[6] = ffma2(xpA, q3.x, a1A[6]); a1B[6] = ffma2(xpB, q3.x, a1B[6]);
            a1A[7] = ffma2(xpA, q3.y, a1A[7]); a1B[7] = ffma2(xpB, q3.y, a1B[7]);
        }

        // ---- per-row tails (statically distinct arrays -> no local-mem demotion) ----
        float ldA_a, ldA_b, ldB_a, ldB_b;
        tail_row(wb, a1A, xrowA, da, db, rowA, initp, out, ldA_a, ldA_b);
        tail_row(wb, a1B, xrowB, da, db, rowB, initp, out, ldB_a, ldB_b);

        // ---- logdet partial sums ----
#pragma unroll
        for (int o = 16; o > 0; o >>= 1){
            ldA_a += __shfl_down_sync(0xffffffffu, ldA_a, o);
            ldA_b += __shfl_down_sync(0xffffffffu, ldA_b, o);
            ldB_a += __shfl_down_sync(0xffffffffu, ldB_a, o);
            ldB_b += __shfl_down_sync(0xffffffffu, ldB_b, o);
        }
        float* red = redf + kp * 16;          // kp-parity buffer: one barrier per kp
        if ((tid & 31) == 0){
            red[warp]      = ldA_a;           // v0: dim da, rows A
            red[4 + warp]  = ldA_b;           // v1: dim db, rows A
            red[8 + warp]  = ldB_a;           // v2: dim da, rows B
            red[12 + warp] = ldB_b;           // v3: dim db, rows B
        }
        __syncthreads();
        if (tid < 8){
            int dimsel = tid >> 2;            // 0: da, 1: db
            int g      = tid & 3;             // 64-row group
            int v      = (g >> 1) * 2 + dimsel;
            int gg     = g & 1;
            float s = red[v * 4 + 2 * gg] + red[v * 4 + 2 * gg + 1];
            int dim = dimsel ? db : da;
            out2[dim * (NR/64) + rowblk * 4 + g] = s;
        }
    }
}

extern "C" void kernel_launch(void* const* d_in, const int* in_sizes, int n_in,
                              void* d_out, int out_size)
{
    const float* x     = (const float*)d_in[0];
    const float* initp = (const float*)d_in[1];
    const float* W1    = (const float*)d_in[2];
    const float* b1    = (const float*)d_in[3];
    const float* W2    = (const float*)d_in[4];
    const float* b2    = (const float*)d_in[5];
    const float* W3    = (const float*)d_in[6];
    const float* b3    = (const float*)d_in[7];
    float* out = (float*)d_out;

    cudaFuncSetAttribute(nsf_ar_kernel,
                         cudaFuncAttributeMaxDynamicSharedMemorySize, SMEM_TOTAL);

    prepack_kernel<<<32, TPB>>>(W1, b1, W2, b2, W3, b3);
    nsf_ar_kernel<<<NRB * NCH, TPB, SMEM_TOTAL>>>(x, initp, out);
}

// round 17
// speedup vs baseline: 2.1595x; 2.1035x over previous
#include <cuda_runtime.h>

#define TPB   128
#define NR    32768
#define DD    64
#define HH    8
#define PP    14
#define KB    5
#define NCH   16           // chunk c owns dim-pairs (2c,2c+1) and (62-2c,63-2c)
#define NRB   128          // row-blocks of 256 rows
#define ROWS  256          // rows per CTA (2 per thread)
#define BBf   5.0f
#define MINW  0.001f
#define MINH  0.001f
#define MIND  0.001f
#define BLOB  736          // u64 per pair blob: w2[64] w3[128] b1[8] b2[8] b3[16] w1[<=504]
#define OFF_W2 0
#define OFF_W3 64
#define OFF_B1 192
#define OFF_B2 200
#define OFF_B3 208
#define OFF_W1 224

typedef unsigned long long u64;

// prepacked weights: 32 blobs (pidx = kp*16 + chunk)
__device__ __align__(16) u64 g_pack[32 * BLOB];
// transposed x: g_xt[d][n], written by prepack_x each launch
__device__ __align__(16) float g_xt[DD * NR];

__device__ __forceinline__ u64 ffma2(u64 a, u64 b, u64 c){
    u64 d; asm("fma.rn.f32x2 %0, %1, %2, %3;" : "=l"(d) : "l"(a), "l"(b), "l"(c)); return d;
}
__device__ __forceinline__ u64 pack2(float lo, float hi){
    u64 d; asm("mov.b64 %0, {%1, %2};" : "=l"(d) : "f"(lo), "f"(hi)); return d;
}
__device__ __forceinline__ void unpack2(u64 v, float& lo, float& hi){
    asm("mov.b64 {%0, %1}, %2;" : "=f"(lo), "=f"(hi) : "l"(v));
}
__device__ __forceinline__ float tanh_fast(float x){
    float y; asm("tanh.approx.f32 %0, %1;" : "=f"(y) : "f"(x)); return y;
}
__device__ __forceinline__ unsigned smem_u32(const void* p){
    return (unsigned)__cvta_generic_to_shared(p);
}
__device__ __forceinline__ void mbar_init(unsigned a, unsigned cnt){
    asm volatile("mbarrier.init.shared.b64 [%0], %1;" :: "r"(a), "r"(cnt) : "memory");
}
__device__ __forceinline__ void mbar_expect_tx(unsigned a, unsigned bytes){
    asm volatile("mbarrier.arrive.expect_tx.shared.b64 _, [%0], %1;" :: "r"(a), "r"(bytes) : "memory");
}
__device__ __forceinline__ void mbar_wait(unsigned a, unsigned phase){
    asm volatile(
        "{\n\t.reg .pred P;\n\t"
        "WAITLP_%=:\n\t"
        "mbarrier.try_wait.parity.acquire.cta.shared::cta.b64 P, [%0], %1, 0x989680;\n\t"
        "@P bra.uni WAITDN_%=;\n\t"
        "bra.uni WAITLP_%=;\n\t"
        "WAITDN_%=:\n\t}"
        :: "r"(a), "r"(phase) : "memory");
}
__device__ __forceinline__ void bulk_g2s(unsigned dst, const void* src, unsigned bytes, unsigned mbar){
    asm volatile(
        "cp.async.bulk.shared::cta.global.mbarrier::complete_tx::bytes [%0], [%1], %2, [%3];"
        :: "r"(dst), "l"(src), "r"(bytes), "r"(mbar) : "memory");
}

// ---------------- prepack_x: x[n][64] -> g_xt[d][n] (exact transpose) ----------------
__global__ void prepack_x(const float* __restrict__ x)
{
    __shared__ float t[32][33];
    const int n0 = blockIdx.x * 32;
    const int d0 = blockIdx.y * 32;
    const int tx = threadIdx.x, ty = threadIdx.y;   // 32 x 8
#pragma unroll
    for (int k = 0; k < 4; k++)
        t[ty + k * 8][tx] = x[(size_t)(n0 + ty + k * 8) * DD + d0 + tx];
    __syncthreads();
#pragma unroll
    for (int k = 0; k < 4; k++)
        g_xt[(size_t)(d0 + ty + k * 8) * NR + n0 + tx] = t[tx][ty + k * 8];
}

// ---------------- prepack_w: interleave (lo,hi) weight pairs for adjacent dims ----------------
__global__ void prepack_w(const float* __restrict__ W1, const float* __restrict__ b1,
                          const float* __restrict__ W2, const float* __restrict__ b2,
                          const float* __restrict__ W3, const float* __restrict__ b3)
{
    const int pidx  = blockIdx.x;        // kp*16 + chunk
    const int kp    = pidx >> 4;
    const int chunk = pidx & 15;
    const int da = kp ? (62 - 2 * chunk) : (2 * chunk);   // pair (da, da+1)
    const int la = da - 1;               // lo-lane l-index, may be -1
    const int lh = da;                   // hi-lane l-index
    u64* dst = g_pack + (size_t)pidx * BLOB;
    const int tid = threadIdx.x;

    if (tid < 64){
        float lo = (la >= 0) ? W2[la * 64 + tid] : 0.f;
        dst[OFF_W2 + tid] = pack2(lo, W2[lh * 64 + tid]);
    }
    if (tid < 128){                      // w3: 8 rows x 16 padded cols
        int g = tid >> 4, c = tid & 15;
        u64 v = 0ULL;
        if (c < PP){
            float lo = (la >= 0) ? W3[la * (HH*PP) + g * PP + c] : 0.f;
            v = pack2(lo, W3[lh * (HH*PP) + g * PP + c]);
        }
        dst[OFF_W3 + tid] = v;
    }
    if (tid < HH){
        float l1v = (la >= 0) ? b1[la * HH + tid] : 0.f;
        dst[OFF_B1 + tid] = pack2(l1v, b1[lh * HH + tid]);
        float l2v = (la >= 0) ? b2[la * HH + tid] : 0.f;
        dst[OFF_B2 + tid] = pack2(l2v, b2[lh * HH + tid]);
    }
    if (tid < 16){
        u64 v = 0ULL;
        if (tid < PP){
            float lo = (la >= 0) ? b3[la * PP + tid] : 0.f;
            v = pack2(lo, b3[lh * PP + tid]);
        }
        dst[OFF_B3 + tid] = v;
    }
    const int n1 = (da + 1) * HH;        // W1 rows j = 0..da
    const float* W1a = W1 + (size_t)la * (63*HH);
    const float* W1b = W1 + (size_t)lh * (63*HH);
    for (int e = tid; e < n1; e += blockDim.x){
        float lo = (la >= 0) ? W1a[e] : 0.f;   // input W1 is pre-masked (rows > la are 0)
        dst[OFF_W1 + e] = pack2(lo, W1b[e]);
    }
}

// Two independent RQS evaluations, interleaved for 2-way ILP through MUFU chains.
__device__ __forceinline__ void rqs_eval2(const float* pa, float xa,
                                          const float* pb, float xb,
                                          float& za, float& lda,
                                          float& zb, float& ldb)
{
    bool ina = (xa >= -BBf) && (xa <= BBf);
    bool inb = (xb >= -BBf) && (xb <= BBf);
    float xca = fminf(fmaxf(xa, -BBf), BBf);
    float xcb = fminf(fmaxf(xb, -BBf), BBf);

    float ewa[KB], eha[KB], ewb[KB], ehb[KB];
    float swa = 0.f, sha = 0.f, swb = 0.f, shb = 0.f;
#pragma unroll
    for (int k = 0; k < KB; k++){
        ewa[k] = __expf(pa[k]);      ewb[k] = __expf(pb[k]);
        swa += ewa[k];               swb += ewb[k];
    }
#pragma unroll
    for (int k = 0; k < KB; k++){
        eha[k] = __expf(pa[KB + k]); ehb[k] = __expf(pb[KB + k]);
        sha += eha[k];               shb += ehb[k];
    }
    float aWa = __fdividef(1.0f - KB * MINW, swa);
    float aWb = __fdividef(1.0f - KB * MINW, swb);
    float aHa = __fdividef(1.0f - KB * MINH, sha);
    float aHb = __fdividef(1.0f - KB * MINH, shb);

    float cwa = -BBf, cha = -BBf, cwb = -BBf, chb = -BBf;
    float icwa = -BBf, icha = -BBf, ibwa = 1.f, iha = 1.f;
    float icwb = -BBf, ichb = -BBf, ibwb = 1.f, ihb = 1.f;
    float duLa = 0.f, duRa = 0.f, duLb = 0.f, duRb = 0.f;
    bool fba = true, lba = false, fbb = true, lbb = false;
#pragma unroll
    for (int k = 0; k < KB; k++){
        float nwa = (k == KB-1) ? BBf : cwa + 2.0f * BBf * (MINW + aWa * ewa[k]);
        float nwb = (k == KB-1) ? BBf : cwb + 2.0f * BBf * (MINW + aWb * ewb[k]);
        float nha = (k == KB-1) ? BBf : cha + 2.0f * BBf * (MINH + aHa * eha[k]);
        float nhb = (k == KB-1) ? BBf : chb + 2.0f * BBf * (MINH + aHb * ehb[k]);
        bool ca = (k == 0) || (xca >= cwa);
        bool cb = (k == 0) || (xcb >= cwb);
        if (ca){
            icwa = cwa; icha = cha; ibwa = nwa - cwa; iha = nha - cha;
            fba = (k == 0); lba = (k == KB-1);
            duLa = (k == 0)    ? 0.f : pa[2*KB + k - 1];
            duRa = (k == KB-1) ? 0.f : pa[2*KB + k];
        }
        if (cb){
            icwb = cwb; ichb = chb; ibwb = nwb - cwb; ihb = nhb - chb;
            fbb = (k == 0); lbb = (k == KB-1);
            duLb = (k == 0)    ? 0.f : pb[2*KB + k - 1];
            duRb = (k == KB-1) ? 0.f : pb[2*KB + k];
        }
        cwa = nwa; cha = nha; cwb = nwb; chb = nhb;
    }
    float idva  = fba ? 1.0f : (MIND + __logf(1.0f + __expf(duLa)));
    float idvb  = fbb ? 1.0f : (MIND + __logf(1.0f + __expf(duLb)));
    float idp1a = lba ? 1.0f : (MIND + __logf(1.0f + __expf(duRa)));
    float idp1b = lbb ? 1.0f : (MIND + __logf(1.0f + __expf(duRb)));

    float rba = __fdividef(1.0f, ibwa);
    float rbb = __fdividef(1.0f, ibwb);
    float tha = (xca - icwa) * rba;
    float thb = (xcb - icwb) * rbb;
    float idla = iha * rba;
    float idlb = ihb * rbb;
    float tma = tha * (1.0f - tha);
    float tmb = thb * (1.0f - thb);
    float t2a = tha * tha;
    float t2b = thb * thb;
    float numa = iha * (idla * t2a + idva * tma);
    float numb = ihb * (idlb * t2b + idvb * tmb);
    float dena = idla + (idva + idp1a - 2.0f * idla) * tma;
    float denb = idlb + (idvb + idp1b - 2.0f * idlb) * tmb;
    float outa = icha + __fdividef(numa, dena);
    float outb = ichb + __fdividef(numb, denb);
    float oma = 1.0f - tha;
    float omb = 1.0f - thb;
    float dna = idla * idla * (idp1a * t2a + 2.0f * idla * tma + idva * oma * oma);
    float dnb = idlb * idlb * (idp1b * t2b + 2.0f * idlb * tmb + idvb * omb * omb);
    float lva = __logf(dna) - 2.0f * __logf(dena);
    float lvb = __logf(dnb) - 2.0f * __logf(denb);

    za  = ina ? outa : xa;
    zb  = inb ? outb : xb;
    lda = ina ? lva  : 0.0f;
    ldb = inb ? lvb  : 0.0f;
}

// Tail for one row: tanh -> layer2 -> layer3 -> both splines.
__device__ __forceinline__ void tail_row(const u64* __restrict__ wb,
                                         const u64 (&a1)[HH],
                                         float x_da, float x_db,
                                         int da, int db, int row,
                                         const float* __restrict__ initp,
                                         float* __restrict__ out,
                                         float& ld_a, float& ld_b)
{
    u64 a1t[HH];
#pragma unroll
    for (int h = 0; h < HH; h++){
        float lo, hi; unpack2(a1[h], lo, hi);
        a1t[h] = pack2(tanh_fast(lo), tanh_fast(hi));
    }

    u64 a2[HH];
#pragma unroll
    for (int g = 0; g < HH; g++) a2[g] = wb[OFF_B2 + g];
#pragma unroll
    for (int h = 0; h < HH; h++){
        u64 hv = a1t[h];
        const ulonglong2* wp = reinterpret_cast<const ulonglong2*>(wb + OFF_W2 + h * 8);
        ulonglong2 q0 = wp[0], q1 = wp[1], q2 = wp[2], q3 = wp[3];
        a2[0] = ffma2(hv, q0.x, a2[0]); a2[1] = ffma2(hv, q0.y, a2[1]);
        a2[2] = ffma2(hv, q1.x, a2[2]); a2[3] = ffma2(hv, q1.y, a2[3]);
        a2[4] = ffma2(hv, q2.x, a2[4]); a2[5] = ffma2(hv, q2.y, a2[5]);
        a2[6] = ffma2(hv, q3.x, a2[6]); a2[7] = ffma2(hv, q3.y, a2[7]);
    }
#pragma unroll
    for (int g = 0; g < HH; g++){
        float lo, hi; unpack2(a2[g], lo, hi);
        a2[g] = pack2(tanh_fast(lo), tanh_fast(hi));
    }

    u64 pu[16];
#pragma unroll
    for (int c = 0; c < 16; c++) pu[c] = wb[OFF_B3 + c];
#pragma unroll
    for (int g = 0; g < HH; g++){
        u64 gv = a2[g];
        const ulonglong2* wp = reinterpret_cast<const ulonglong2*>(wb + OFF_W3 + g * 16);
        ulonglong2 q0 = wp[0], q1 = wp[1], q2 = wp[2], q3 = wp[3];
        ulonglong2 q4 = wp[4], q5 = wp[5], q6 = wp[6];
        pu[0]  = ffma2(gv, q0.x, pu[0]);  pu[1]  = ffma2(gv, q0.y, pu[1]);
        pu[2]  = ffma2(gv, q1.x, pu[2]);  pu[3]  = ffma2(gv, q1.y, pu[3]);
        pu[4]  = ffma2(gv, q2.x, pu[4]);  pu[5]  = ffma2(gv, q2.y, pu[5]);
        pu[6]  = ffma2(gv, q3.x, pu[6]);  pu[7]  = ffma2(gv, q3.y, pu[7]);
        pu[8]  = ffma2(gv, q4.x, pu[8]);  pu[9]  = ffma2(gv, q4.y, pu[9]);
        pu[10] = ffma2(gv, q5.x, pu[10]); pu[11] = ffma2(gv, q5.y, pu[11]);
        pu[12] = ffma2(gv, q6.x, pu[12]); pu[13] = ffma2(gv, q6.y, pu[13]);
    }

    float pa[PP], pb[PP];
#pragma unroll
    for (int c = 0; c < PP; c++) unpack2(pu[c], pa[c], pb[c]);
    if (da == 0){
#pragma unroll
        for (int c = 0; c < PP; c++) pa[c] = initp[c];
    }

    float za, lda, zb, ldb;
    rqs_eval2(pa, x_da, pb, x_db, za, lda, zb, ldb);
    out[(size_t)da * NR + row] = za;
    out[(size_t)db * NR + row] = zb;
    ld_a = lda; ld_b = ldb;
}

__global__ __launch_bounds__(TPB, 4)
void nsf_ar_kernel(const float* __restrict__ initp, float* __restrict__ out)
{
    __shared__ __align__(16) u64 wbuf[960];          // both blobs, exact constant total
    __shared__ __align__(16) u64 park[HH][TPB + 1];  // a1B parking (self-access only)
    __shared__ __align__(8)  u64 mbar[1];
    __shared__ float redf[2][16];

    const int tid    = threadIdx.x;
    const int warp   = tid >> 5;
    const int bid    = blockIdx.x;          // 0..2047
    const int chunk  = bid & (NCH - 1);     // 0..15
    const int rowblk = bid >> 4;            // 0..127
    const int row0   = rowblk * ROWS;
    const int rowA   = row0 + tid;
    const int rowB   = row0 + 128 + tid;

    const unsigned a_mbar = smem_u32(mbar);
    if (tid == 0) mbar_init(a_mbar, 1);
    __syncthreads();

    const int da0 = 2 * chunk;              // kp0 pair (da0, da0+1)
    const int da1 = 62 - 2 * chunk;         // kp1 pair (da1, da1+1)
    const unsigned S0u = 224 + (da0 + 1) * HH;
    const unsigned S1u = 224 + (da1 + 1) * HH;

    if (tid == 0){
        asm volatile("fence.proxy.async.shared::cta;" ::: "memory");
        mbar_expect_tx(a_mbar, (S0u + S1u) * 8);
        bulk_g2s(smem_u32(wbuf),           (const void*)(g_pack + (size_t)chunk * BLOB),        S0u * 8, a_mbar);
        bulk_g2s(smem_u32(wbuf) + S0u * 8, (const void*)(g_pack + (size_t)(16 + chunk) * BLOB), S1u * 8, a_mbar);
    }
    mbar_wait(a_mbar, 0);

    const float* xA = g_xt + rowA;          // column j at xA[j*NR]
    const float* xB = g_xt + rowB;
    float* out2 = out + (size_t)NR * DD;

#pragma unroll
    for (int kp = 0; kp < 2; kp++){
        const int da = kp ? da1 : da0;
        const int db = da + 1;
        const u64* wb = kp ? (wbuf + S0u) : wbuf;

        // ---- layer 1: rows A and B share every weight fetch; x from global transposed ----
        u64 a1A[HH], a1B[HH];
#pragma unroll
        for (int h = 0; h < HH; h++){ u64 b = wb[OFF_B1 + h]; a1A[h] = b; a1B[h] = b; }
#pragma unroll 4
        for (int j = 0; j <= da; j++){
            float xa = __ldg(xA + (size_t)j * NR);
            float xb = __ldg(xB + (size_t)j * NR);
            u64 xpA = pack2(xa, xa), xpB = pack2(xb, xb);
            const ulonglong2* wp = reinterpret_cast<const ulonglong2*>(wb + OFF_W1 + j * 8);
            ulonglong2 q0 = wp[0], q1 = wp[1], q2 = wp[2], q3 = wp[3];
            a1A[0] = ffma2(xpA, q0.x, a1A[0]); a1B[0] = ffma2(xpB, q0.x, a1B[0]);
            a1A[1] = ffma2(xpA, q0.y, a1A[1]); a1B[1] = ffma2(xpB, q0.y, a1B[1]);
            a1A[2] = ffma2(xpA, q1.x, a1A[2]); a1B[2] = ffma2(xpB, q1.x, a1B[2]);
            a1A[3] = ffma2(xpA, q1.y, a1A[3]); a1B[3] = ffma2(xpB, q1.y, a1B[3]);
            a1A[4] = ffma2(xpA, q2.x, a1A[4]); a1B[4] = ffma2(xpB, q2.x, a1B[4]);
            a1A[5] = ffma2(xpA, q2.y, a1A[5]); a1B[5] = ffma2(xpB, q2.y, a1B[5]);
            a1A[6] = ffma2(xpA, q3.x, a1A[6]); a1B[6] = ffma2(xpB, q3.x, a1B[6]);
            a1A[7] = ffma2(xpA, q3.y, a1A[7]); a1B[7] = ffma2(xpB, q3.y, a1B[7]);
        }

        // park row-B accumulators in smem (self-slot only: no sync, kills live range)
#pragma unroll
        for (int h = 0; h < HH; h++) park[h][tid] = a1B[h];

        // ---- tail A ----
        float xAda = __ldg(xA + (size_t)da * NR);
        float xAdb = __ldg(xA + (size_t)db * NR);
        float ldA_a, ldA_b;
        tail_row(wb, a1A, xAda, xAdb, da, db, rowA, initp, out, ldA_a, ldA_b);

        // ---- tail B (reload parked accumulators) ----
        u64 a1R[HH];
#pragma unroll
        for (int h = 0; h < HH; h++) a1R[h] = park[h][tid];
        float xBda = __ldg(xB + (size_t)da * NR);
        float xBdb = __ldg(xB + (size_t)db * NR);
        float ldB_a, ldB_b;
        tail_row(wb, a1R, xBda, xBdb, da, db, rowB, initp, out, ldB_a, ldB_b);

        // ---- logdet partial sums (64-row groups) ----
#pragma unroll
        for (int o = 16; o > 0; o >>= 1){
            ldA_a += __shfl_down_sync(0xffffffffu, ldA_a, o);
            ldA_b += __shfl_down_sync(0xffffffffu, ldA_b, o);
            ldB_a += __shfl_down_sync(0xffffffffu, ldB_a, o);
            ldB_b += __shfl_down_sync(0xffffffffu, ldB_b, o);
        }
        float* red = redf[kp];
        if ((tid & 31) == 0){
            red[warp]      = ldA_a;           // v0: dim da, rows A
            red[4 + warp]  = ldA_b;           // v1: dim db, rows A
            red[8 + warp]  = ldB_a;           // v2: dim da, rows B
            red[12 + warp] = ldB_b;           // v3: dim db, rows B
        }
        __syncthreads();
        if (tid < 8){
            int dimsel = tid >> 2;            // 0: da, 1: db
            int g      = tid & 3;             // 64-row group within 256-row tile
            int v      = (g >> 1) * 2 + dimsel;
            int gg     = g & 1;
            float s = red[v * 4 + 2 * gg] + red[v * 4 + 2 * gg + 1];
            int dim = dimsel ? db : da;
            out2[dim * (NR/64) + rowblk * 4 + g] = s;
        }
    }
}

extern "C" void kernel_launch(void* const* d_in, const int* in_sizes, int n_in,
                              void* d_out, int out_size)
{
    const float* x     = (const float*)d_in[0];
    const float* initp = (const float*)d_in[1];
    const float* W1    = (const float*)d_in[2];
    const float* b1    = (const float*)d_in[3];
    const float* W2    = (const float*)d_in[4];
    const float* b2    = (const float*)d_in[5];
    const float* W3    = (const float*)d_in[6];
    const float* b3    = (const float*)d_in[7];
    float* out = (float*)d_out;

    dim3 tgrid(NR / 32, DD / 32);
    dim3 tblk(32, 8);
    prepack_x<<<tgrid, tblk>>>(x);
    prepack_w<<<32, TPB>>>(W1, b1, W2, b2, W3, b3);
    nsf_ar_kernel<<<NRB * NCH, TPB>>>(initp, out);
}